// round 5
// baseline (speedup 1.0000x reference)
#include <cuda_runtime.h>
#include <math.h>

#define NPART 262144
#define NNB   4194304

// ---------------- static device scratch (no allocations allowed) ------------
__device__ float4 g_A1[NPART];   // a1.xyz, w = base_type (int bits)
__device__ float4 g_A2[NPART];
__device__ float4 g_A3[NPART];
__device__ float4 g_BACK[NPART];
__device__ float4 g_BASE[NPART];
__device__ float4 g_STCK[NPART];
__device__ float4 g_CM[NPART];
__device__ int2   g_list[NNB];
__device__ int    g_count;
__device__ double g_energy;

// ---------------- model constants ------------------------------------------
#define EXCL_EPS 2.0f
#define PI_F 3.14159265358979f
// precomputed f1 shifts: (exp(-a*(rc-r0))-1)^2
#define SHIFT_STCK 0.90290461f   // a=6, rc-r0=0.5
#define SHIFT_HYDR 0.88207775f   // a=8, rc-r0=0.35
// compaction cutoff: max site-site cutoff 0.783 + 2*0.4 site offset = 1.583
#define R2CUT 2.5100f            // (1.5843)^2, small safety margin

// ---------------- smoothed potential pieces --------------------------------
__device__ __forceinline__ float acosc(float c) {
    return acosf(fminf(fmaxf(c, -0.999999f), 0.999999f));
}

__device__ __forceinline__ float fexcl(float r, float sig, float rstar, float b, float rc) {
    if (r >= rc) return 0.f;
    if (r < rstar) {
        float t = __fdividef(sig, r);
        float t2 = t * t;
        float s6 = t2 * t2 * t2;
        return 4.f * EXCL_EPS * (s6 * s6 - s6);
    }
    float x = r - rc;
    return EXCL_EPS * b * x * x;
}

__device__ __forceinline__ float f1f(float r, float a, float r0, float shift,
                                     float rlow, float rhigh, float blow, float rclow,
                                     float bhigh, float rchigh) {
    if (r > rlow && r < rhigh) {
        float ex = __expf(-a * (r - r0)) - 1.f;
        return ex * ex - shift;
    }
    if (r > rclow && r <= rlow) { float x = r - rclow;  return blow  * x * x; }
    if (r >= rhigh && r < rchigh) { float x = r - rchigh; return bhigh * x * x; }
    return 0.f;
}

__device__ __forceinline__ float f2f(float r, float k, float r0, float rc,
                                     float rlow, float rhigh, float blow, float rclow,
                                     float bhigh, float rchigh) {
    if (r > rlow && r < rhigh) {
        float x = r - r0, y = rc - r0;
        return 0.5f * k * (x * x - y * y);
    }
    if (r > rclow && r <= rlow) { float x = r - rclow;  return k * blow  * x * x; }
    if (r >= rhigh && r < rchigh) { float x = r - rchigh; return k * bhigh * x * x; }
    return 0.f;
}

__device__ __forceinline__ float f4f(float th, float a, float t0, float ts, float b, float tc) {
    float dt = fabsf(th - t0);
    if (dt < ts) return 1.f - a * dt * dt;
    if (dt < tc) { float x = tc - dt; return b * x * x; }
    return 0.f;
}

__device__ __forceinline__ float f5f(float x) {
    if (x > 0.f) return 1.f;
    if (x > -0.65f) return 1.f - 2.f * x * x;
    if (x > -0.769231f) { float t = -0.769231f - x; return 10.9032f * t * t; }
    return 0.f;
}

__device__ __forceinline__ void min_image(float& dx, float& dy, float& dz,
                                          float bx, float by, float bz) {
    dx -= bx * rintf(__fdividef(dx, bx));
    dy -= by * rintf(__fdividef(dy, by));
    dz -= bz * rintf(__fdividef(dz, bz));
}

// block-wide float reduction -> one double atomic per block
__device__ __forceinline__ void block_accum(float v) {
    #pragma unroll
    for (int o = 16; o > 0; o >>= 1) v += __shfl_down_sync(0xffffffffu, v, o);
    __shared__ float sw[32];
    int lane = threadIdx.x & 31, warp = threadIdx.x >> 5;
    if (lane == 0) sw[warp] = v;
    __syncthreads();
    if (warp == 0) {
        int nw = (blockDim.x + 31) >> 5;
        float t = (lane < nw) ? sw[lane] : 0.f;
        #pragma unroll
        for (int o = 16; o > 0; o >>= 1) t += __shfl_down_sync(0xffffffffu, t, o);
        if (lane == 0) atomicAdd(&g_energy, (double)t);
    }
}

// ---------------- kernels ---------------------------------------------------
__global__ void k_init() { g_count = 0; g_energy = 0.0; }

__global__ void k_frames(const float* __restrict__ pos, const float* __restrict__ quat,
                         const int* __restrict__ types, int n) {
    int i = blockIdx.x * blockDim.x + threadIdx.x;
    if (i >= n) return;
    float w = quat[4*i], x = quat[4*i+1], y = quat[4*i+2], z = quat[4*i+3];
    float inv = rsqrtf(w*w + x*x + y*y + z*z + 1e-12f);
    w *= inv; x *= inv; y *= inv; z *= inv;
    float a1x = 1.f - 2.f*(y*y + z*z), a1y = 2.f*(x*y + w*z), a1z = 2.f*(x*z - w*y);
    float a2x = 2.f*(x*y - w*z), a2y = 1.f - 2.f*(x*x + z*z), a2z = 2.f*(y*z + w*x);
    float a3x = 2.f*(x*z + w*y), a3y = 2.f*(y*z - w*x), a3z = 1.f - 2.f*(x*x + y*y);
    float px = pos[3*i], py = pos[3*i+1], pz = pos[3*i+2];
    g_A1[i]   = make_float4(a1x, a1y, a1z, __int_as_float(types[i]));
    g_A2[i]   = make_float4(a2x, a2y, a2z, 0.f);
    g_A3[i]   = make_float4(a3x, a3y, a3z, 0.f);
    g_BACK[i] = make_float4(px - 0.4f*a1x,  py - 0.4f*a1y,  pz - 0.4f*a1z,  0.f);
    g_STCK[i] = make_float4(px + 0.34f*a1x, py + 0.34f*a1y, pz + 0.34f*a1z, 0.f);
    g_BASE[i] = make_float4(px + 0.4f*a1x,  py + 0.4f*a1y,  pz + 0.4f*a1z,  0.f);
    g_CM[i]   = make_float4(px, py, pz, 0.f);
}

__global__ void k_bonded(const int* __restrict__ bp, const float* __restrict__ seps,
                         const float* __restrict__ box, int nb) {
    int k = blockIdx.x * blockDim.x + threadIdx.x;
    float e = 0.f;
    if (k < nb) {
        int i = bp[2*k], j = bp[2*k+1];
        float bx = __ldg(box), by = __ldg(box+1), bz = __ldg(box+2);
        float4 BKi = g_BACK[i], BKj = g_BACK[j];
        float4 BSi = g_BASE[i], BSj = g_BASE[j];
        float4 STi = g_STCK[i], STj = g_STCK[j];
        float4 A3i = g_A3[i],   A3j = g_A3[j];
        float4 A2i = g_A2[i],   A2j = g_A2[j];

        // FENE (back-back)
        float dbx = BKj.x - BKi.x, dby = BKj.y - BKi.y, dbz = BKj.z - BKi.z;
        min_image(dbx, dby, dbz, bx, by, bz);
        float rb2 = dbx*dbx + dby*dby + dbz*dbz + 1e-12f;
        float rb = sqrtf(rb2);
        float u = (rb - 0.7525f) * 4.f;           // /FENE_DELTA (0.25)
        float arg = fminf(u * u, 1.f - 1e-6f);
        e += -log1pf(-arg);                       // -0.5*FENE_EPS = -1

        // bonded excluded volume
        {
            float dx = BSj.x - BSi.x, dy = BSj.y - BSi.y, dz = BSj.z - BSi.z;
            min_image(dx, dy, dz, bx, by, bz);
            float r = sqrtf(dx*dx + dy*dy + dz*dz + 1e-12f);
            e += fexcl(r, 0.33f, 0.32f, 4119.70450017f, 0.335388426126f);
        }
        {
            float dx = BSj.x - BKi.x, dy = BSj.y - BKi.y, dz = BSj.z - BKi.z;
            min_image(dx, dy, dz, bx, by, bz);
            float r = sqrtf(dx*dx + dy*dy + dz*dz + 1e-12f);
            e += fexcl(r, 0.515f, 0.5f, 2047.42812499f, 0.52329943261f);
        }
        {
            float dx = BKj.x - BSi.x, dy = BKj.y - BSi.y, dz = BKj.z - BSi.z;
            min_image(dx, dy, dz, bx, by, bz);
            float r = sqrtf(dx*dx + dy*dy + dz*dz + 1e-12f);
            e += fexcl(r, 0.515f, 0.5f, 2047.42812499f, 0.52329943261f);
        }

        // stacking
        float dsx = STj.x - STi.x, dsy = STj.y - STi.y, dsz = STj.z - STi.z;
        min_image(dsx, dsy, dsz, bx, by, bz);
        float d2 = dsx*dsx + dsy*dsy + dsz*dsz + 1e-12f;
        float r = sqrtf(d2);
        float invr = rsqrtf(d2);
        float rhx = dsx*invr, rhy = dsy*invr, rhz = dsz*invr;
        float t4 = acosc(A3i.x*A3j.x + A3i.y*A3j.y + A3i.z*A3j.z);
        float t5 = acosc(A3j.x*rhx + A3j.y*rhy + A3j.z*rhz);
        float t6 = acosc(-(A3i.x*rhx + A3i.y*rhy + A3i.z*rhz));
        float invrb = rsqrtf(rb2);
        float rbhx = dbx*invrb, rbhy = dby*invrb, rbhz = dbz*invrb;
        float cphi1 = A2i.x*rbhx + A2i.y*rbhy + A2i.z*rbhz;
        float cphi2 = A2j.x*rbhx + A2j.y*rbhy + A2j.z*rbhz;
        float f1s = f1f(r, 6.0f, 0.4f, SHIFT_STCK, 0.32f, 0.75f, -0.68f, 0.26f, -12.6f, 0.8f);
        e += seps[k] * f1s
           * f4f(t4, 1.3f, 0.f, 0.8f, 6.4f, 0.961538f)
           * f4f(t5, 0.9f, 0.f, 0.95f, 3.9f, 1.16959f)
           * f4f(t6, 0.9f, 0.f, 0.95f, 3.9f, 1.16959f)
           * f5f(cphi1) * f5f(cphi2);
    }
    block_accum(e);
}

__global__ void k_compact(const int* __restrict__ nbp, const float* __restrict__ box, int nnb) {
    __shared__ int s_wcnt[16];
    __shared__ int s_base;
    int p = blockIdx.x * blockDim.x + threadIdx.x;
    int lane = threadIdx.x & 31, warp = threadIdx.x >> 5;
    bool pred = false;
    int2 pr = make_int2(0, 0);
    if (p < nnb) {
        pr = ((const int2*)nbp)[p];
        float4 ci = g_CM[pr.x], cj = g_CM[pr.y];
        float bx = __ldg(box), by = __ldg(box+1), bz = __ldg(box+2);
        float dx = cj.x - ci.x, dy = cj.y - ci.y, dz = cj.z - ci.z;
        min_image(dx, dy, dz, bx, by, bz);
        pred = (dx*dx + dy*dy + dz*dz) < R2CUT;
    }
    unsigned m = __ballot_sync(0xffffffffu, pred);
    if (lane == 0) s_wcnt[warp] = __popc(m);
    __syncthreads();
    if (threadIdx.x == 0) {
        int tot = 0;
        #pragma unroll
        for (int w = 0; w < 16; w++) { int c = s_wcnt[w]; s_wcnt[w] = tot; tot += c; }
        s_base = atomicAdd(&g_count, tot);
    }
    __syncthreads();
    if (pred) {
        int idx = s_base + s_wcnt[warp] + __popc(m & ((1u << lane) - 1u));
        g_list[idx] = pr;
    }
}

__global__ void k_nonbonded(const float* __restrict__ heps, const float* __restrict__ box) {
    int total = g_count;
    float bx = __ldg(box), by = __ldg(box+1), bz = __ldg(box+2);
    float e = 0.f;
    for (int idx = blockIdx.x * blockDim.x + threadIdx.x; idx < total;
         idx += gridDim.x * blockDim.x) {
        int2 pr = g_list[idx];
        int i = pr.x, j = pr.y;
        float4 A1i = g_A1[i],   A1j = g_A1[j];
        float4 A3i = g_A3[i],   A3j = g_A3[j];
        float4 BAi = g_BASE[i], BAj = g_BASE[j];
        float4 BKi = g_BACK[i], BKj = g_BACK[j];

        // excluded volume: back-back, base-base, back->base, base->back
        {
            float dx = BKj.x - BKi.x, dy = BKj.y - BKi.y, dz = BKj.z - BKi.z;
            min_image(dx, dy, dz, bx, by, bz);
            float r = sqrtf(dx*dx + dy*dy + dz*dz + 1e-12f);
            e += fexcl(r, 0.7f, 0.675f, 892.016223343f, 0.711879214356f);
        }
        {
            float dx = BAj.x - BKi.x, dy = BAj.y - BKi.y, dz = BAj.z - BKi.z;
            min_image(dx, dy, dz, bx, by, bz);
            float r = sqrtf(dx*dx + dy*dy + dz*dz + 1e-12f);
            e += fexcl(r, 0.515f, 0.5f, 2047.42812499f, 0.52329943261f);
        }
        {
            float dx = BKj.x - BAi.x, dy = BKj.y - BAi.y, dz = BKj.z - BAi.z;
            min_image(dx, dy, dz, bx, by, bz);
            float r = sqrtf(dx*dx + dy*dy + dz*dz + 1e-12f);
            e += fexcl(r, 0.515f, 0.5f, 2047.42812499f, 0.52329943261f);
        }

        // base-base distance (excl + HB + CRST)
        float dx = BAj.x - BAi.x, dy = BAj.y - BAi.y, dz = BAj.z - BAi.z;
        min_image(dx, dy, dz, bx, by, bz);
        float d2 = dx*dx + dy*dy + dz*dz + 1e-12f;
        float r = sqrtf(d2);
        e += fexcl(r, 0.33f, 0.32f, 4119.70450017f, 0.335388426126f);

        float f1h = f1f(r, 8.0f, 0.4f, SHIFT_HYDR, 0.34f, 0.7f, -126.2f, 0.276f, -7.87f, 0.783f);
        float f2c = f2f(r, 47.5f, 0.575f, 0.675f, 0.495f, 0.655f, -0.888f, 0.45f, -0.888f, 0.68f);

        float d11 = A1i.x*A1j.x + A1i.y*A1j.y + A1i.z*A1j.z;
        float d33 = A3i.x*A3j.x + A3i.y*A3j.y + A3i.z*A3j.z;
        float t1 = acosc(-d11);
        float t4 = acosc(d33);

        if (f1h != 0.f || f2c != 0.f) {
            float invr = rsqrtf(d2);
            float rhx = dx*invr, rhy = dy*invr, rhz = dz*invr;
            float t2 = acosc(-(A1j.x*rhx + A1j.y*rhy + A1j.z*rhz));
            float t3 = acosc(A1i.x*rhx + A1i.y*rhy + A1i.z*rhz);
            float t7 = acosc(-(A3j.x*rhx + A3j.y*rhy + A3j.z*rhz));
            float t8 = acosc(A3i.x*rhx + A3i.y*rhy + A3i.z*rhz);
            float f4t7  = f4f(t7,        4.0f, 1.5707963267948966f, 0.45f, 17.0526f, 0.555556f);
            float f4t7m = f4f(PI_F - t7, 4.0f, 1.5707963267948966f, 0.45f, 17.0526f, 0.555556f);
            if (f1h != 0.f) {
                int bti = __float_as_int(A1i.w), btj = __float_as_int(A1j.w);
                float eps = __ldg(&heps[bti * 4 + btj]);
                e += eps * f1h
                   * f4f(t1, 1.5f, 0.f, 0.7f, 4.16038f, 0.952381f)
                   * f4f(t2, 1.5f, 0.f, 0.7f, 4.16038f, 0.952381f)
                   * f4f(t3, 1.5f, 0.f, 0.7f, 4.16038f, 0.952381f)
                   * f4f(t4, 0.46f, PI_F, 0.7f, 1.14813f, 3.0f)
                   * f4t7
                   * f4f(t8, 4.0f, 1.5707963267948966f, 0.45f, 17.0526f, 0.555556f);
            }
            if (f2c != 0.f) {
                e += f2c
                   * f4f(t1, 2.25f, 0.791592653589793f, 0.58f, 10.9032f, 0.766284f)
                   * f4f(t4, 1.5f, 0.f, 0.7f, 4.16038f, 0.952381f)
                   * (f4t7 + f4t7m);
            }
        }

        // coaxial stacking (stck-stck distance)
        float4 STi = g_STCK[i], STj = g_STCK[j];
        float dcx = STj.x - STi.x, dcy = STj.y - STi.y, dcz = STj.z - STi.z;
        min_image(dcx, dcy, dcz, bx, by, bz);
        float c2 = dcx*dcx + dcy*dcy + dcz*dcz + 1e-12f;
        float rcx = sqrtf(c2);
        float f2x = f2f(rcx, 46.0f, 0.4f, 0.6f, 0.22f, 0.58f, -0.7f, 0.2f, -0.7f, 0.62f);
        if (f2x != 0.f) {
            float4 A2i = g_A2[i], A2j = g_A2[j];
            float invc = rsqrtf(c2);
            float ct5 = acosc(A3j.x*dcx*invc + A3j.y*dcy*invc + A3j.z*dcz*invc);
            float cphi3 = A2i.x*A2j.x + A2i.y*A2j.y + A2i.z*A2j.z;
            e += f2x
               * f4f(t1, 2.0f, 2.592f, 0.65f, 10.9032f, 0.766284f)
               * f4f(t4, 1.3f, 0.f, 0.8f, 6.4f, 0.961538f)
               * f4f(ct5, 0.9f, 0.f, 0.95f, 3.9f, 1.16959f)
               * f5f(cphi3);
        }
    }
    block_accum(e);
}

__global__ void k_final(float* __restrict__ out) { out[0] = (float)g_energy; }

// ---------------- launch ----------------------------------------------------
extern "C" void kernel_launch(void* const* d_in, const int* in_sizes, int n_in,
                              void* d_out, int out_size) {
    const float* pos   = (const float*)d_in[0];
    const float* quat  = (const float*)d_in[1];
    const float* seps  = (const float*)d_in[2];
    const float* heps  = (const float*)d_in[3];
    const float* box   = (const float*)d_in[4];
    const int*   bp    = (const int*)d_in[5];
    const int*   nbp   = (const int*)d_in[6];
    const int*   types = (const int*)d_in[7];

    int n   = in_sizes[0] / 3;
    int nb  = in_sizes[5] / 2;
    int nnb = in_sizes[6] / 2;
    if (n > NPART) n = NPART;
    if (nnb > NNB) nnb = NNB;

    k_init<<<1, 1>>>();
    k_frames<<<(n + 255) / 256, 256>>>(pos, quat, types, n);
    k_bonded<<<(nb + 255) / 256, 256>>>(bp, seps, box, nb);
    k_compact<<<(nnb + 511) / 512, 512>>>(nbp, box, nnb);
    k_nonbonded<<<1184, 256>>>(heps, box);
    k_final<<<1, 1>>>((float*)d_out);
}

// round 6
// speedup vs baseline: 1.0635x; 1.0635x over previous
#include <cuda_runtime.h>
#include <math.h>

#define NPART 262144
#define NNB   4194304

// ---------------- static device scratch -------------------------------------
// Per-particle packed record, 96 B = 3 L2 sectors:
//   g_P0[2i]   = back (sector 0 lo)
//   g_P0[2i+1] = base (sector 0 hi)
//   g_REST[4i+0] = stck, [4i+1] = a1 (w = base_type bits), [4i+2] = a3, [4i+3] = a2
__device__ float4 g_P0[2 * NPART];
__device__ float4 g_REST[4 * NPART];
__device__ int2   g_list[NNB];
__device__ int    g_count;
__device__ double g_energy;

// ---------------- model constants -------------------------------------------
#define EXCL_EPS 2.0f
#define PI_F 3.14159265358979f
#define SHIFT_STCK 0.90290461f   // (exp(-6*0.5)-1)^2
#define SHIFT_HYDR 0.88207775f   // (exp(-8*0.35)-1)^2
#define GATE_D2 0.613089f        // 0.783^2 : exact gate for all angular terms

// ---------------- potential pieces ------------------------------------------
__device__ __forceinline__ float acosc(float c) {
    return acosf(fminf(fmaxf(c, -0.999999f), 0.999999f));
}

// excluded volume from squared distance (sqrt only in the rare smoothing shell)
__device__ __forceinline__ float fexcl_d2(float d2, float sig2, float rstar2,
                                          float b, float rc, float rc2) {
    if (d2 >= rc2) return 0.f;
    if (d2 < rstar2) {
        float s2 = __fdividef(sig2, d2);
        float s6 = s2 * s2 * s2;
        return 4.f * EXCL_EPS * (s6 * s6 - s6);
    }
    float x = sqrtf(d2) - rc;
    return EXCL_EPS * b * x * x;
}

__device__ __forceinline__ float f1f(float r, float a, float r0, float shift,
                                     float rlow, float rhigh, float blow, float rclow,
                                     float bhigh, float rchigh) {
    if (r > rlow && r < rhigh) {
        float ex = __expf(-a * (r - r0)) - 1.f;
        return ex * ex - shift;
    }
    if (r > rclow && r <= rlow) { float x = r - rclow;  return blow  * x * x; }
    if (r >= rhigh && r < rchigh) { float x = r - rchigh; return bhigh * x * x; }
    return 0.f;
}

__device__ __forceinline__ float f2f(float r, float k, float r0, float rc,
                                     float rlow, float rhigh, float blow, float rclow,
                                     float bhigh, float rchigh) {
    if (r > rlow && r < rhigh) {
        float x = r - r0, y = rc - r0;
        return 0.5f * k * (x * x - y * y);
    }
    if (r > rclow && r <= rlow) { float x = r - rclow;  return k * blow  * x * x; }
    if (r >= rhigh && r < rchigh) { float x = r - rchigh; return k * bhigh * x * x; }
    return 0.f;
}

__device__ __forceinline__ float f4f(float th, float a, float t0, float ts, float b, float tc) {
    float dt = fabsf(th - t0);
    if (dt < ts) return 1.f - a * dt * dt;
    if (dt < tc) { float x = tc - dt; return b * x * x; }
    return 0.f;
}

__device__ __forceinline__ float f5f(float x) {
    if (x > 0.f) return 1.f;
    if (x > -0.65f) return 1.f - 2.f * x * x;
    if (x > -0.769231f) { float t = -0.769231f - x; return 10.9032f * t * t; }
    return 0.f;
}

// block-wide float reduction -> one double atomic per block
__device__ __forceinline__ void block_accum(float v) {
    #pragma unroll
    for (int o = 16; o > 0; o >>= 1) v += __shfl_down_sync(0xffffffffu, v, o);
    __shared__ float sw[32];
    int lane = threadIdx.x & 31, warp = threadIdx.x >> 5;
    if (lane == 0) sw[warp] = v;
    __syncthreads();
    if (warp == 0) {
        int nw = (blockDim.x + 31) >> 5;
        float t = (lane < nw) ? sw[lane] : 0.f;
        #pragma unroll
        for (int o = 16; o > 0; o >>= 1) t += __shfl_down_sync(0xffffffffu, t, o);
        if (lane == 0) atomicAdd(&g_energy, (double)t);
    }
}

// ---------------- kernels ----------------------------------------------------
__global__ void k_frames(const float* __restrict__ pos, const float* __restrict__ quat,
                         const int* __restrict__ types, int n) {
    int i = blockIdx.x * blockDim.x + threadIdx.x;
    if (i == 0) { g_count = 0; g_energy = 0.0; }
    if (i >= n) return;
    float w = quat[4*i], x = quat[4*i+1], y = quat[4*i+2], z = quat[4*i+3];
    float inv = rsqrtf(w*w + x*x + y*y + z*z + 1e-12f);
    w *= inv; x *= inv; y *= inv; z *= inv;
    float a1x = 1.f - 2.f*(y*y + z*z), a1y = 2.f*(x*y + w*z), a1z = 2.f*(x*z - w*y);
    float a2x = 2.f*(x*y - w*z), a2y = 1.f - 2.f*(x*x + z*z), a2z = 2.f*(y*z + w*x);
    float a3x = 2.f*(x*z + w*y), a3y = 2.f*(y*z - w*x), a3z = 1.f - 2.f*(x*x + y*y);
    float px = pos[3*i], py = pos[3*i+1], pz = pos[3*i+2];
    g_P0[2*i]     = make_float4(px - 0.4f*a1x,  py - 0.4f*a1y,  pz - 0.4f*a1z,  0.f); // back
    g_P0[2*i+1]   = make_float4(px + 0.4f*a1x,  py + 0.4f*a1y,  pz + 0.4f*a1z,  0.f); // base
    g_REST[4*i]   = make_float4(px + 0.34f*a1x, py + 0.34f*a1y, pz + 0.34f*a1z, 0.f); // stck
    g_REST[4*i+1] = make_float4(a1x, a1y, a1z, __int_as_float(types[i]));
    g_REST[4*i+2] = make_float4(a3x, a3y, a3z, 0.f);
    g_REST[4*i+3] = make_float4(a2x, a2y, a2z, 0.f);
}

__global__ void k_bonded(const int* __restrict__ bp, const float* __restrict__ seps,
                         const float* __restrict__ box, int nb) {
    int k = blockIdx.x * blockDim.x + threadIdx.x;
    float e = 0.f;
    if (k < nb) {
        int i = bp[2*k], j = bp[2*k+1];
        float bx = __ldg(box), by = __ldg(box+1), bz = __ldg(box+2);
        float ibx = 1.f/bx, iby = 1.f/by, ibz = 1.f/bz;
        float4 BKi = g_P0[2*i],   BKj = g_P0[2*j];
        float4 BSi = g_P0[2*i+1], BSj = g_P0[2*j+1];
        float4 STi = g_REST[4*i],   STj = g_REST[4*j];
        float4 A3i = g_REST[4*i+2], A3j = g_REST[4*j+2];
        float4 A2i = g_REST[4*i+3], A2j = g_REST[4*j+3];

        // FENE (back-back)
        float dbx = BKj.x - BKi.x, dby = BKj.y - BKi.y, dbz = BKj.z - BKi.z;
        dbx -= bx*rintf(dbx*ibx); dby -= by*rintf(dby*iby); dbz -= bz*rintf(dbz*ibz);
        float rb2 = dbx*dbx + dby*dby + dbz*dbz + 1e-12f;
        float rb = sqrtf(rb2);
        float u = (rb - 0.7525f) * 4.f;
        float arg = fminf(u * u, 1.f - 1e-6f);
        e += -log1pf(-arg);   // -0.5*FENE_EPS = -1

        // bonded excluded volume (base-base, base_j-back_i, back_j-base_i)
        {
            float dx = BSj.x - BSi.x, dy = BSj.y - BSi.y, dz = BSj.z - BSi.z;
            dx -= bx*rintf(dx*ibx); dy -= by*rintf(dy*iby); dz -= bz*rintf(dz*ibz);
            float d2 = dx*dx + dy*dy + dz*dz + 1e-12f;
            e += fexcl_d2(d2, 0.33f*0.33f, 0.32f*0.32f, 4119.70450017f,
                          0.335388426126f, 0.335388426126f*0.335388426126f);
        }
        {
            float dx = BSj.x - BKi.x, dy = BSj.y - BKi.y, dz = BSj.z - BKi.z;
            dx -= bx*rintf(dx*ibx); dy -= by*rintf(dy*iby); dz -= bz*rintf(dz*ibz);
            float d2 = dx*dx + dy*dy + dz*dz + 1e-12f;
            e += fexcl_d2(d2, 0.515f*0.515f, 0.25f, 2047.42812499f,
                          0.52329943261f, 0.52329943261f*0.52329943261f);
        }
        {
            float dx = BKj.x - BSi.x, dy = BKj.y - BSi.y, dz = BKj.z - BSi.z;
            dx -= bx*rintf(dx*ibx); dy -= by*rintf(dy*iby); dz -= bz*rintf(dz*ibz);
            float d2 = dx*dx + dy*dy + dz*dz + 1e-12f;
            e += fexcl_d2(d2, 0.515f*0.515f, 0.25f, 2047.42812499f,
                          0.52329943261f, 0.52329943261f*0.52329943261f);
        }

        // stacking
        float dsx = STj.x - STi.x, dsy = STj.y - STi.y, dsz = STj.z - STi.z;
        dsx -= bx*rintf(dsx*ibx); dsy -= by*rintf(dsy*iby); dsz -= bz*rintf(dsz*ibz);
        float d2 = dsx*dsx + dsy*dsy + dsz*dsz + 1e-12f;
        float r = sqrtf(d2);
        float invr = rsqrtf(d2);
        float rhx = dsx*invr, rhy = dsy*invr, rhz = dsz*invr;
        float t4 = acosc(A3i.x*A3j.x + A3i.y*A3j.y + A3i.z*A3j.z);
        float t5 = acosc(A3j.x*rhx + A3j.y*rhy + A3j.z*rhz);
        float t6 = acosc(-(A3i.x*rhx + A3i.y*rhy + A3i.z*rhz));
        float invrb = rsqrtf(rb2);
        float rbhx = dbx*invrb, rbhy = dby*invrb, rbhz = dbz*invrb;
        float cphi1 = A2i.x*rbhx + A2i.y*rbhy + A2i.z*rbhz;
        float cphi2 = A2j.x*rbhx + A2j.y*rbhy + A2j.z*rbhz;
        float f1s = f1f(r, 6.0f, 0.4f, SHIFT_STCK, 0.32f, 0.75f, -0.68f, 0.26f, -12.6f, 0.8f);
        e += seps[k] * f1s
           * f4f(t4, 1.3f, 0.f, 0.8f, 6.4f, 0.961538f)
           * f4f(t5, 0.9f, 0.f, 0.95f, 3.9f, 1.16959f)
           * f4f(t6, 0.9f, 0.f, 0.95f, 3.9f, 1.16959f)
           * f5f(cphi1) * f5f(cphi2);
    }
    block_accum(e);
}

// Compact: U=4 pairs/thread. Computes ALL excluded-volume energy exactly and
// emits only pairs with base-base d2 < 0.783^2 (exact gate for hb/crst/coax).
__global__ __launch_bounds__(256)
void k_compact(const int* __restrict__ nbp, const float* __restrict__ box, int nnb) {
    const int t = threadIdx.x;
    const int lane = t & 31, wid = t >> 5;
    const int tile = blockIdx.x * 1024;
    float bx = __ldg(box), by = __ldg(box+1), bz = __ldg(box+2);
    float ibx = 1.f/bx, iby = 1.f/by, ibz = 1.f/bz;

    const int2* p2 = (const int2*)nbp;
    int2 pr[4];
    bool ok[4];
    #pragma unroll
    for (int k = 0; k < 4; k++) {
        int idx = tile + k * 256 + t;
        ok[k] = idx < nnb;
        pr[k] = ok[k] ? __ldg(&p2[idx]) : make_int2(0, 0);
    }

    float e = 0.f;
    unsigned pmask = 0u;
    #pragma unroll
    for (int k = 0; k < 4; k++) {
        if (!ok[k]) continue;
        int i = pr[k].x, j = pr[k].y;
        float4 bk_i = __ldg(&g_P0[2*i]), bs_i = __ldg(&g_P0[2*i+1]);
        float4 bk_j = __ldg(&g_P0[2*j]), bs_j = __ldg(&g_P0[2*j+1]);

        // base-base diff with exact min-image; reuse wrap for siblings
        float dx = bs_j.x - bs_i.x, dy = bs_j.y - bs_i.y, dz = bs_j.z - bs_i.z;
        float cx = bx * rintf(dx * ibx), cy = by * rintf(dy * iby), cz = bz * rintf(dz * ibz);
        dx -= cx; dy -= cy; dz -= cz;
        float d2bb = dx*dx + dy*dy + dz*dz + 1e-12f;

        float ex2 = bk_j.x - bk_i.x - cx, ey2 = bk_j.y - bk_i.y - cy, ez2 = bk_j.z - bk_i.z - cz;
        float d2kk = ex2*ex2 + ey2*ey2 + ez2*ez2 + 1e-12f;

        float mx = bs_j.x - bk_i.x - cx, my = bs_j.y - bk_i.y - cy, mz = bs_j.z - bk_i.z - cz;
        float d2m1 = mx*mx + my*my + mz*mz + 1e-12f;

        float nx = bk_j.x - bs_i.x - cx, ny = bk_j.y - bs_i.y - cy, nz = bk_j.z - bs_i.z - cz;
        float d2m2 = nx*nx + ny*ny + nz*nz + 1e-12f;

        e += fexcl_d2(d2kk, 0.49f, 0.455625f, 892.016223343f,
                      0.711879214356f, 0.711879214356f*0.711879214356f);
        e += fexcl_d2(d2bb, 0.1089f, 0.1024f, 4119.70450017f,
                      0.335388426126f, 0.335388426126f*0.335388426126f);
        e += fexcl_d2(d2m1, 0.265225f, 0.25f, 2047.42812499f,
                      0.52329943261f, 0.52329943261f*0.52329943261f);
        e += fexcl_d2(d2m2, 0.265225f, 0.25f, 2047.42812499f,
                      0.52329943261f, 0.52329943261f*0.52329943261f);

        if (d2bb < GATE_D2) pmask |= 1u << k;
    }

    // unordered dense compaction: warp scan + one global atomic per block
    int cnt = __popc(pmask);
    int scan = cnt;
    #pragma unroll
    for (int o = 1; o < 32; o <<= 1) {
        int v = __shfl_up_sync(0xffffffffu, scan, o);
        if (lane >= o) scan += v;
    }
    __shared__ int s_wb[8];
    __shared__ int s_base;
    if (lane == 31) s_wb[wid] = scan;
    __syncthreads();
    if (t == 0) {
        int s = 0;
        #pragma unroll
        for (int w = 0; w < 8; w++) { int c = s_wb[w]; s_wb[w] = s; s += c; }
        s_base = atomicAdd(&g_count, s);
    }
    __syncthreads();
    int off = s_base + s_wb[wid] + (scan - cnt);
    #pragma unroll
    for (int k = 0; k < 4; k++)
        if (pmask & (1u << k)) g_list[off++] = pr[k];

    block_accum(e);
}

// Angular terms (HB + CRST + coaxial) on the exactly-gated survivor list.
__global__ void k_nonbonded(const float* __restrict__ heps, const float* __restrict__ box) {
    int total = g_count;
    float bx = __ldg(box), by = __ldg(box+1), bz = __ldg(box+2);
    float ibx = 1.f/bx, iby = 1.f/by, ibz = 1.f/bz;
    float e = 0.f;
    for (int idx = blockIdx.x * blockDim.x + threadIdx.x; idx < total;
         idx += gridDim.x * blockDim.x) {
        int2 pr = g_list[idx];
        int i = pr.x, j = pr.y;
        float4 bs_i = __ldg(&g_P0[2*i+1]),  bs_j = __ldg(&g_P0[2*j+1]);
        float4 STi = __ldg(&g_REST[4*i]),   STj = __ldg(&g_REST[4*j]);
        float4 A1i = __ldg(&g_REST[4*i+1]), A1j = __ldg(&g_REST[4*j+1]);
        float4 A3i = __ldg(&g_REST[4*i+2]), A3j = __ldg(&g_REST[4*j+2]);
        float4 A2i = __ldg(&g_REST[4*i+3]), A2j = __ldg(&g_REST[4*j+3]);

        float dx = bs_j.x - bs_i.x, dy = bs_j.y - bs_i.y, dz = bs_j.z - bs_i.z;
        dx -= bx*rintf(dx*ibx); dy -= by*rintf(dy*iby); dz -= bz*rintf(dz*ibz);
        float d2 = dx*dx + dy*dy + dz*dz + 1e-12f;
        float r = sqrtf(d2);

        float f1h = f1f(r, 8.0f, 0.4f, SHIFT_HYDR, 0.34f, 0.7f, -126.2f, 0.276f, -7.87f, 0.783f);
        float f2c = f2f(r, 47.5f, 0.575f, 0.675f, 0.495f, 0.655f, -0.888f, 0.45f, -0.888f, 0.68f);

        float t1 = acosc(-(A1i.x*A1j.x + A1i.y*A1j.y + A1i.z*A1j.z));
        float t4 = acosc(A3i.x*A3j.x + A3i.y*A3j.y + A3i.z*A3j.z);

        if (f1h != 0.f || f2c != 0.f) {
            float invr = rsqrtf(d2);
            float rhx = dx*invr, rhy = dy*invr, rhz = dz*invr;
            float t2 = acosc(-(A1j.x*rhx + A1j.y*rhy + A1j.z*rhz));
            float t3 = acosc(A1i.x*rhx + A1i.y*rhy + A1i.z*rhz);
            float t7 = acosc(-(A3j.x*rhx + A3j.y*rhy + A3j.z*rhz));
            float t8 = acosc(A3i.x*rhx + A3i.y*rhy + A3i.z*rhz);
            float f4t7  = f4f(t7,        4.0f, 1.5707963267948966f, 0.45f, 17.0526f, 0.555556f);
            float f4t7m = f4f(PI_F - t7, 4.0f, 1.5707963267948966f, 0.45f, 17.0526f, 0.555556f);
            if (f1h != 0.f) {
                int bti = __float_as_int(A1i.w), btj = __float_as_int(A1j.w);
                float eps = __ldg(&heps[bti * 4 + btj]);
                e += eps * f1h
                   * f4f(t1, 1.5f, 0.f, 0.7f, 4.16038f, 0.952381f)
                   * f4f(t2, 1.5f, 0.f, 0.7f, 4.16038f, 0.952381f)
                   * f4f(t3, 1.5f, 0.f, 0.7f, 4.16038f, 0.952381f)
                   * f4f(t4, 0.46f, PI_F, 0.7f, 1.14813f, 3.0f)
                   * f4t7
                   * f4f(t8, 4.0f, 1.5707963267948966f, 0.45f, 17.0526f, 0.555556f);
            }
            if (f2c != 0.f) {
                e += f2c
                   * f4f(t1, 2.25f, 0.791592653589793f, 0.58f, 10.9032f, 0.766284f)
                   * f4f(t4, 1.5f, 0.f, 0.7f, 4.16038f, 0.952381f)
                   * (f4t7 + f4t7m);
            }
        }

        // coaxial stacking (stck-stck)
        float dcx = STj.x - STi.x, dcy = STj.y - STi.y, dcz = STj.z - STi.z;
        dcx -= bx*rintf(dcx*ibx); dcy -= by*rintf(dcy*iby); dcz -= bz*rintf(dcz*ibz);
        float c2 = dcx*dcx + dcy*dcy + dcz*dcz + 1e-12f;
        float rcx = sqrtf(c2);
        float f2x = f2f(rcx, 46.0f, 0.4f, 0.6f, 0.22f, 0.58f, -0.7f, 0.2f, -0.7f, 0.62f);
        if (f2x != 0.f) {
            float invc = rsqrtf(c2);
            float ct5 = acosc(A3j.x*dcx*invc + A3j.y*dcy*invc + A3j.z*dcz*invc);
            float cphi3 = A2i.x*A2j.x + A2i.y*A2j.y + A2i.z*A2j.z;
            e += f2x
               * f4f(t1, 2.0f, 2.592f, 0.65f, 10.9032f, 0.766284f)
               * f4f(t4, 1.3f, 0.f, 0.8f, 6.4f, 0.961538f)
               * f4f(ct5, 0.9f, 0.f, 0.95f, 3.9f, 1.16959f)
               * f5f(cphi3);
        }
    }
    block_accum(e);
}

__global__ void k_final(float* __restrict__ out) { out[0] = (float)g_energy; }

// ---------------- launch -----------------------------------------------------
extern "C" void kernel_launch(void* const* d_in, const int* in_sizes, int n_in,
                              void* d_out, int out_size) {
    const float* pos   = (const float*)d_in[0];
    const float* quat  = (const float*)d_in[1];
    const float* seps  = (const float*)d_in[2];
    const float* heps  = (const float*)d_in[3];
    const float* box   = (const float*)d_in[4];
    const int*   bp    = (const int*)d_in[5];
    const int*   nbp   = (const int*)d_in[6];
    const int*   types = (const int*)d_in[7];

    int n   = in_sizes[0] / 3;
    int nb  = in_sizes[5] / 2;
    int nnb = in_sizes[6] / 2;
    if (n > NPART) n = NPART;
    if (nnb > NNB) nnb = NNB;

    k_frames<<<(n + 255) / 256, 256>>>(pos, quat, types, n);
    k_bonded<<<(nb + 255) / 256, 256>>>(bp, seps, box, nb);
    k_compact<<<(nnb + 1023) / 1024, 256>>>(nbp, box, nnb);
    k_nonbonded<<<1184, 256>>>(heps, box);
    k_final<<<1, 1>>>((float*)d_out);
}

// round 7
// speedup vs baseline: 1.0920x; 1.0268x over previous
#include <cuda_runtime.h>
#include <math.h>

#define NPART 262144
#define NNB   4194304
#define GRID_BOND 1024          // NPART/256 blocks for bonded (nb = NPART-1)
#define GRID_P2   2048          // stage2 fixed grid
#define NSLOT     (GRID_BOND + GRID_P2)   // 3072 partial slots

// ---------------- static device scratch -------------------------------------
__device__ float4 g_CM[NPART];          // center of mass (gate only)
__device__ float4 g_P0[2 * NPART];      // [2i]=back, [2i+1]=base (one 32B sector)
__device__ float4 g_REST[4 * NPART];    // stck, a1(w=type), a3, a2
__device__ int2   g_list[NNB];
__device__ int    g_count;
__device__ double g_part[NSLOT];

// ---------------- constants --------------------------------------------------
#define EXCL_EPS 2.0f
#define PI_F 3.14159265358979f
#define SHIFT_STCK 0.90290461f   // (exp(-6*0.5)-1)^2
#define SHIFT_HYDR 0.88207775f   // (exp(-8*0.35)-1)^2
#define GATE_D2 0.613089f        // 0.783^2 : exact gate for hb/crst/coax
#define R2CUT 2.5100f            // (1.5843)^2 : CM gate (0.783 + 2*0.4 slack)

// ---------------- potential pieces -------------------------------------------
__device__ __forceinline__ float acosc(float c) {
    return acosf(fminf(fmaxf(c, -0.999999f), 0.999999f));
}

__device__ __forceinline__ float fexcl_d2(float d2, float sig2, float rstar2,
                                          float b, float rc, float rc2) {
    if (d2 >= rc2) return 0.f;
    if (d2 < rstar2) {
        float s2 = __fdividef(sig2, d2);
        float s6 = s2 * s2 * s2;
        return 4.f * EXCL_EPS * (s6 * s6 - s6);
    }
    float x = sqrtf(d2) - rc;
    return EXCL_EPS * b * x * x;
}

__device__ __forceinline__ float f1f(float r, float a, float r0, float shift,
                                     float rlow, float rhigh, float blow, float rclow,
                                     float bhigh, float rchigh) {
    if (r > rlow && r < rhigh) {
        float ex = __expf(-a * (r - r0)) - 1.f;
        return ex * ex - shift;
    }
    if (r > rclow && r <= rlow) { float x = r - rclow;  return blow  * x * x; }
    if (r >= rhigh && r < rchigh) { float x = r - rchigh; return bhigh * x * x; }
    return 0.f;
}

__device__ __forceinline__ float f2f(float r, float k, float r0, float rc,
                                     float rlow, float rhigh, float blow, float rclow,
                                     float bhigh, float rchigh) {
    if (r > rlow && r < rhigh) {
        float x = r - r0, y = rc - r0;
        return 0.5f * k * (x * x - y * y);
    }
    if (r > rclow && r <= rlow) { float x = r - rclow;  return k * blow  * x * x; }
    if (r >= rhigh && r < rchigh) { float x = r - rchigh; return k * bhigh * x * x; }
    return 0.f;
}

__device__ __forceinline__ float f4f(float th, float a, float t0, float ts, float b, float tc) {
    float dt = fabsf(th - t0);
    if (dt < ts) return 1.f - a * dt * dt;
    if (dt < tc) { float x = tc - dt; return b * x * x; }
    return 0.f;
}

__device__ __forceinline__ float f5f(float x) {
    if (x > 0.f) return 1.f;
    if (x > -0.65f) return 1.f - 2.f * x * x;
    if (x > -0.769231f) { float t = -0.769231f - x; return 10.9032f * t * t; }
    return 0.f;
}

// block-wide float reduction -> ONE plain store to this block's partial slot
__device__ __forceinline__ void block_accum_slot(float v, double* slot) {
    #pragma unroll
    for (int o = 16; o > 0; o >>= 1) v += __shfl_down_sync(0xffffffffu, v, o);
    __shared__ float sw[32];
    int lane = threadIdx.x & 31, warp = threadIdx.x >> 5;
    if (lane == 0) sw[warp] = v;
    __syncthreads();
    if (warp == 0) {
        int nw = (blockDim.x + 31) >> 5;
        float t = (lane < nw) ? sw[lane] : 0.f;
        #pragma unroll
        for (int o = 16; o > 0; o >>= 1) t += __shfl_down_sync(0xffffffffu, t, o);
        if (lane == 0) *slot = (double)t;
    }
}

// ---------------- kernels -----------------------------------------------------
__global__ void k_frames(const float* __restrict__ pos, const float* __restrict__ quat,
                         const int* __restrict__ types, int n) {
    int i = blockIdx.x * blockDim.x + threadIdx.x;
    if (i == 0) g_count = 0;
    if (i >= n) return;
    float w = quat[4*i], x = quat[4*i+1], y = quat[4*i+2], z = quat[4*i+3];
    float inv = rsqrtf(w*w + x*x + y*y + z*z + 1e-12f);
    w *= inv; x *= inv; y *= inv; z *= inv;
    float a1x = 1.f - 2.f*(y*y + z*z), a1y = 2.f*(x*y + w*z), a1z = 2.f*(x*z - w*y);
    float a2x = 2.f*(x*y - w*z), a2y = 1.f - 2.f*(x*x + z*z), a2z = 2.f*(y*z + w*x);
    float a3x = 2.f*(x*z + w*y), a3y = 2.f*(y*z - w*x), a3z = 1.f - 2.f*(x*x + y*y);
    float px = pos[3*i], py = pos[3*i+1], pz = pos[3*i+2];
    g_CM[i]       = make_float4(px, py, pz, 0.f);
    g_P0[2*i]     = make_float4(px - 0.4f*a1x,  py - 0.4f*a1y,  pz - 0.4f*a1z,  0.f);
    g_P0[2*i+1]   = make_float4(px + 0.4f*a1x,  py + 0.4f*a1y,  pz + 0.4f*a1z,  0.f);
    g_REST[4*i]   = make_float4(px + 0.34f*a1x, py + 0.34f*a1y, pz + 0.34f*a1z, 0.f);
    g_REST[4*i+1] = make_float4(a1x, a1y, a1z, __int_as_float(types[i]));
    g_REST[4*i+2] = make_float4(a3x, a3y, a3z, 0.f);
    g_REST[4*i+3] = make_float4(a2x, a2y, a2z, 0.f);
}

__global__ void k_bonded(const int* __restrict__ bp, const float* __restrict__ seps, int nb) {
    int k = blockIdx.x * blockDim.x + threadIdx.x;
    float e = 0.f;
    if (k < nb) {
        int i = bp[2*k], j = bp[2*k+1];
        float4 BKi = g_P0[2*i],   BKj = g_P0[2*j];
        float4 BSi = g_P0[2*i+1], BSj = g_P0[2*j+1];
        float4 STi = g_REST[4*i],   STj = g_REST[4*j];
        float4 A3i = g_REST[4*i+2], A3j = g_REST[4*j+2];
        float4 A2i = g_REST[4*i+3], A2j = g_REST[4*j+3];

        // FENE (back-back) — no wrap possible (see span analysis)
        float dbx = BKj.x - BKi.x, dby = BKj.y - BKi.y, dbz = BKj.z - BKi.z;
        float rb2 = dbx*dbx + dby*dby + dbz*dbz + 1e-12f;
        float rb = sqrtf(rb2);
        float u = (rb - 0.7525f) * 4.f;
        float arg = fminf(u * u, 1.f - 1e-6f);
        e += -log1pf(-arg);

        // bonded excluded volume
        {
            float dx = BSj.x - BSi.x, dy = BSj.y - BSi.y, dz = BSj.z - BSi.z;
            float d2 = dx*dx + dy*dy + dz*dz + 1e-12f;
            e += fexcl_d2(d2, 0.1089f, 0.1024f, 4119.70450017f,
                          0.335388426126f, 0.335388426126f*0.335388426126f);
        }
        {
            float dx = BSj.x - BKi.x, dy = BSj.y - BKi.y, dz = BSj.z - BKi.z;
            float d2 = dx*dx + dy*dy + dz*dz + 1e-12f;
            e += fexcl_d2(d2, 0.265225f, 0.25f, 2047.42812499f,
                          0.52329943261f, 0.52329943261f*0.52329943261f);
        }
        {
            float dx = BKj.x - BSi.x, dy = BKj.y - BSi.y, dz = BKj.z - BSi.z;
            float d2 = dx*dx + dy*dy + dz*dz + 1e-12f;
            e += fexcl_d2(d2, 0.265225f, 0.25f, 2047.42812499f,
                          0.52329943261f, 0.52329943261f*0.52329943261f);
        }

        // stacking
        float dsx = STj.x - STi.x, dsy = STj.y - STi.y, dsz = STj.z - STi.z;
        float d2 = dsx*dsx + dsy*dsy + dsz*dsz + 1e-12f;
        float r = sqrtf(d2);
        float invr = rsqrtf(d2);
        float rhx = dsx*invr, rhy = dsy*invr, rhz = dsz*invr;
        float t4 = acosc(A3i.x*A3j.x + A3i.y*A3j.y + A3i.z*A3j.z);
        float t5 = acosc(A3j.x*rhx + A3j.y*rhy + A3j.z*rhz);
        float t6 = acosc(-(A3i.x*rhx + A3i.y*rhy + A3i.z*rhz));
        float invrb = rsqrtf(rb2);
        float rbhx = dbx*invrb, rbhy = dby*invrb, rbhz = dbz*invrb;
        float cphi1 = A2i.x*rbhx + A2i.y*rbhy + A2i.z*rbhz;
        float cphi2 = A2j.x*rbhx + A2j.y*rbhy + A2j.z*rbhz;
        float f1s = f1f(r, 6.0f, 0.4f, SHIFT_STCK, 0.32f, 0.75f, -0.68f, 0.26f, -12.6f, 0.8f);
        e += seps[k] * f1s
           * f4f(t4, 1.3f, 0.f, 0.8f, 6.4f, 0.961538f)
           * f4f(t5, 0.9f, 0.f, 0.95f, 3.9f, 1.16959f)
           * f4f(t6, 0.9f, 0.f, 0.95f, 3.9f, 1.16959f)
           * f5f(cphi1) * f5f(cphi2);
    }
    block_accum_slot(e, &g_part[blockIdx.x]);
}

// Stage 1: pure CM gate. 2 scattered wavefronts/pair — the hard floor.
__global__ __launch_bounds__(512)
void k_gate(const int* __restrict__ nbp, int nnb) {
    const int t = threadIdx.x;
    const int lane = t & 31, wid = t >> 5;
    const int tile = blockIdx.x * 2048;
    const int2* p2 = (const int2*)nbp;

    int2 pr[4];
    float4 ci[4], cj[4];
    #pragma unroll
    for (int k = 0; k < 4; k++) {
        int idx = tile + k * 512 + t;
        pr[k] = (idx < nnb) ? __ldg(&p2[idx]) : make_int2(0, 0);
    }
    #pragma unroll
    for (int k = 0; k < 4; k++) {
        ci[k] = __ldg(&g_CM[pr[k].x]);
        cj[k] = __ldg(&g_CM[pr[k].y]);
    }

    unsigned pmask = 0u;
    #pragma unroll
    for (int k = 0; k < 4; k++) {
        int idx = tile + k * 512 + t;
        float dx = cj[k].x - ci[k].x, dy = cj[k].y - ci[k].y, dz = cj[k].z - ci[k].z;
        float d2 = dx*dx + dy*dy + dz*dz;
        if (d2 < R2CUT && idx < nnb) pmask |= 1u << k;
    }

    int cnt = __popc(pmask);
    int scan = cnt;
    #pragma unroll
    for (int o = 1; o < 32; o <<= 1) {
        int v = __shfl_up_sync(0xffffffffu, scan, o);
        if (lane >= o) scan += v;
    }
    __shared__ int s_wb[16];
    __shared__ int s_base;
    if (lane == 31) s_wb[wid] = scan;
    __syncthreads();
    if (t == 0) {
        int s = 0;
        #pragma unroll
        for (int w = 0; w < 16; w++) { int c = s_wb[w]; s_wb[w] = s; s += c; }
        s_base = atomicAdd(&g_count, s);
    }
    __syncthreads();
    int off = s_base + s_wb[wid] + (scan - cnt);
    #pragma unroll
    for (int k = 0; k < 4; k++)
        if (pmask & (1u << k)) g_list[off++] = pr[k];
}

// Stage 2: excluded volume (exact) on gate survivors + predicated angular block.
__global__ __launch_bounds__(256)
void k_pair(const float* __restrict__ heps) {
    int total = g_count;
    int stride = gridDim.x * blockDim.x;
    float e = 0.f;
    for (int idx = blockIdx.x * blockDim.x + threadIdx.x; idx < total; idx += stride) {
        int2 pr = __ldg(&g_list[idx]);
        int i = pr.x, j = pr.y;
        float4 bk_i = __ldg(&g_P0[2*i]), bs_i = __ldg(&g_P0[2*i+1]);
        float4 bk_j = __ldg(&g_P0[2*j]), bs_j = __ldg(&g_P0[2*j+1]);

        float dx = bs_j.x - bs_i.x, dy = bs_j.y - bs_i.y, dz = bs_j.z - bs_i.z;
        float d2bb = dx*dx + dy*dy + dz*dz + 1e-12f;

        float ex2 = bk_j.x - bk_i.x, ey2 = bk_j.y - bk_i.y, ez2 = bk_j.z - bk_i.z;
        float d2kk = ex2*ex2 + ey2*ey2 + ez2*ez2 + 1e-12f;

        float mx = bs_j.x - bk_i.x, my = bs_j.y - bk_i.y, mz = bs_j.z - bk_i.z;
        float d2m1 = mx*mx + my*my + mz*mz + 1e-12f;

        float nx = bk_j.x - bs_i.x, ny = bk_j.y - bs_i.y, nz = bk_j.z - bs_i.z;
        float d2m2 = nx*nx + ny*ny + nz*nz + 1e-12f;

        e += fexcl_d2(d2kk, 0.49f, 0.455625f, 892.016223343f,
                      0.711879214356f, 0.711879214356f*0.711879214356f);
        e += fexcl_d2(d2bb, 0.1089f, 0.1024f, 4119.70450017f,
                      0.335388426126f, 0.335388426126f*0.335388426126f);
        e += fexcl_d2(d2m1, 0.265225f, 0.25f, 2047.42812499f,
                      0.52329943261f, 0.52329943261f*0.52329943261f);
        e += fexcl_d2(d2m2, 0.265225f, 0.25f, 2047.42812499f,
                      0.52329943261f, 0.52329943261f*0.52329943261f);

        if (d2bb < GATE_D2) {
            float4 STi = __ldg(&g_REST[4*i]),   STj = __ldg(&g_REST[4*j]);
            float4 A1i = __ldg(&g_REST[4*i+1]), A1j = __ldg(&g_REST[4*j+1]);
            float4 A3i = __ldg(&g_REST[4*i+2]), A3j = __ldg(&g_REST[4*j+2]);
            float4 A2i = __ldg(&g_REST[4*i+3]), A2j = __ldg(&g_REST[4*j+3]);

            float r = sqrtf(d2bb);
            float f1h = f1f(r, 8.0f, 0.4f, SHIFT_HYDR, 0.34f, 0.7f, -126.2f, 0.276f, -7.87f, 0.783f);
            float f2c = f2f(r, 47.5f, 0.575f, 0.675f, 0.495f, 0.655f, -0.888f, 0.45f, -0.888f, 0.68f);

            float t1 = acosc(-(A1i.x*A1j.x + A1i.y*A1j.y + A1i.z*A1j.z));
            float t4 = acosc(A3i.x*A3j.x + A3i.y*A3j.y + A3i.z*A3j.z);

            if (f1h != 0.f || f2c != 0.f) {
                float invr = rsqrtf(d2bb);
                float rhx = dx*invr, rhy = dy*invr, rhz = dz*invr;
                float t2 = acosc(-(A1j.x*rhx + A1j.y*rhy + A1j.z*rhz));
                float t3 = acosc(A1i.x*rhx + A1i.y*rhy + A1i.z*rhz);
                float t7 = acosc(-(A3j.x*rhx + A3j.y*rhy + A3j.z*rhz));
                float t8 = acosc(A3i.x*rhx + A3i.y*rhy + A3i.z*rhz);
                float f4t7  = f4f(t7,        4.0f, 1.5707963267948966f, 0.45f, 17.0526f, 0.555556f);
                float f4t7m = f4f(PI_F - t7, 4.0f, 1.5707963267948966f, 0.45f, 17.0526f, 0.555556f);
                if (f1h != 0.f) {
                    int bti = __float_as_int(A1i.w), btj = __float_as_int(A1j.w);
                    float eps = __ldg(&heps[bti * 4 + btj]);
                    e += eps * f1h
                       * f4f(t1, 1.5f, 0.f, 0.7f, 4.16038f, 0.952381f)
                       * f4f(t2, 1.5f, 0.f, 0.7f, 4.16038f, 0.952381f)
                       * f4f(t3, 1.5f, 0.f, 0.7f, 4.16038f, 0.952381f)
                       * f4f(t4, 0.46f, PI_F, 0.7f, 1.14813f, 3.0f)
                       * f4t7
                       * f4f(t8, 4.0f, 1.5707963267948966f, 0.45f, 17.0526f, 0.555556f);
                }
                if (f2c != 0.f) {
                    e += f2c
                       * f4f(t1, 2.25f, 0.791592653589793f, 0.58f, 10.9032f, 0.766284f)
                       * f4f(t4, 1.5f, 0.f, 0.7f, 4.16038f, 0.952381f)
                       * (f4t7 + f4t7m);
                }
            }

            // coaxial stacking (stck-stck)
            float dcx = STj.x - STi.x, dcy = STj.y - STi.y, dcz = STj.z - STi.z;
            float c2 = dcx*dcx + dcy*dcy + dcz*dcz + 1e-12f;
            float rcx = sqrtf(c2);
            float f2x = f2f(rcx, 46.0f, 0.4f, 0.6f, 0.22f, 0.58f, -0.7f, 0.2f, -0.7f, 0.62f);
            if (f2x != 0.f) {
                float invc = rsqrtf(c2);
                float ct5 = acosc(A3j.x*dcx*invc + A3j.y*dcy*invc + A3j.z*dcz*invc);
                float cphi3 = A2i.x*A2j.x + A2i.y*A2j.y + A2i.z*A2j.z;
                e += f2x
                   * f4f(t1, 2.0f, 2.592f, 0.65f, 10.9032f, 0.766284f)
                   * f4f(t4, 1.3f, 0.f, 0.8f, 6.4f, 0.961538f)
                   * f4f(ct5, 0.9f, 0.f, 0.95f, 3.9f, 1.16959f)
                   * f5f(cphi3);
            }
        }
    }
    block_accum_slot(e, &g_part[GRID_BOND + blockIdx.x]);
}

__global__ void k_final(float* __restrict__ out) {
    __shared__ double sd[256];
    double s = 0.0;
    for (int i = threadIdx.x; i < NSLOT; i += 256) s += g_part[i];
    sd[threadIdx.x] = s;
    __syncthreads();
    for (int o = 128; o > 0; o >>= 1) {
        if (threadIdx.x < o) sd[threadIdx.x] += sd[threadIdx.x + o];
        __syncthreads();
    }
    if (threadIdx.x == 0) out[0] = (float)sd[0];
}

// ---------------- launch -------------------------------------------------------
extern "C" void kernel_launch(void* const* d_in, const int* in_sizes, int n_in,
                              void* d_out, int out_size) {
    const float* pos   = (const float*)d_in[0];
    const float* quat  = (const float*)d_in[1];
    const float* seps  = (const float*)d_in[2];
    const float* heps  = (const float*)d_in[3];
    const int*   bp    = (const int*)d_in[5];
    const int*   nbp   = (const int*)d_in[6];
    const int*   types = (const int*)d_in[7];

    int n   = in_sizes[0] / 3;
    int nb  = in_sizes[5] / 2;
    int nnb = in_sizes[6] / 2;
    if (n > NPART) n = NPART;
    if (nnb > NNB) nnb = NNB;

    k_frames<<<(n + 255) / 256, 256>>>(pos, quat, types, n);
    k_bonded<<<GRID_BOND, 256>>>(bp, seps, nb);
    k_gate<<<(nnb + 2047) / 2048, 512>>>(nbp, nnb);
    k_pair<<<GRID_P2, 256>>>(heps);
    k_final<<<1, 256>>>((float*)d_out);
}